// round 2
// baseline (speedup 1.0000x reference)
#include <cuda_runtime.h>
#include <math.h>

#define SEQ 1024
#define BB  64
#define DD  512
#define HH  512

#define NCTA0 32
#define NSL0  16   // HH / NCTA0
#define NCTA1 64
#define NSL1  8    // HH / NCTA1

#define HSS 516    // padded shared row stride for h (bank spread)

// Scratch (allocation-free rule: __device__ globals)
__device__ float g_z0[SEQ * BB * HH];   // x@Wx0 + bx0 + bh0
__device__ float g_h0[SEQ * BB * HH];   // layer-0 hidden history
__device__ int   g_flag0[SEQ];
__device__ int   g_flag1[SEQ];

__device__ __forceinline__ int ld_acq(const int* p) {
    int v;
    asm volatile("ld.acquire.gpu.s32 %0, [%1];" : "=r"(v) : "l"(p) : "memory");
    return v;
}

__global__ void init_flags() {
    int i = blockIdx.x * blockDim.x + threadIdx.x;
    if (i < SEQ) { g_flag0[i] = 0; g_flag1[i] = 0; }
}

// ---------------------------------------------------------------------------
// Precompute Z0 = X @ Wx0 + bx0 + bh0.  M=SEQ*BB=65536, N=512, K=512.
// 64x64 CTA tile, 256 threads, 4x4 micro-tile, K-chunk 16.
// ---------------------------------------------------------------------------
__global__ __launch_bounds__(256) void precompute_z0(
    const float* __restrict__ X,
    const float* __restrict__ W,
    const float* __restrict__ bxv,
    const float* __restrict__ bhv)
{
    __shared__ float As[16][64];
    __shared__ float Bs[16][64];
    const int tid = threadIdx.x;
    const int tx = tid & 15;
    const int ty = tid >> 4;
    const int m0 = blockIdx.x * 64;
    const int n0 = blockIdx.y * 64;
    const int lm = tid >> 2;          // 0..63 (A row)
    const int lk = (tid & 3) << 2;    // 0,4,8,12 (A k group)
    const int lr = tid >> 4;          // 0..15 (B k row)
    const int lc = (tid & 15) << 2;   // B col*4

    float acc[4][4];
#pragma unroll
    for (int i = 0; i < 4; i++)
#pragma unroll
        for (int j = 0; j < 4; j++) acc[i][j] = 0.f;

    for (int kc = 0; kc < DD; kc += 16) {
        float4 a4 = *(const float4*)(X + (size_t)(m0 + lm) * DD + kc + lk);
        float4 b4 = *(const float4*)(W + (size_t)(kc + lr) * HH + n0 + lc);
        As[lk + 0][lm] = a4.x;
        As[lk + 1][lm] = a4.y;
        As[lk + 2][lm] = a4.z;
        As[lk + 3][lm] = a4.w;
        *(float4*)&Bs[lr][lc] = b4;
        __syncthreads();
#pragma unroll
        for (int kk = 0; kk < 16; kk++) {
            float4 av = *(const float4*)&As[kk][ty << 2];
            float4 bv = *(const float4*)&Bs[kk][tx << 2];
            float ar[4] = {av.x, av.y, av.z, av.w};
            float br[4] = {bv.x, bv.y, bv.z, bv.w};
#pragma unroll
            for (int i = 0; i < 4; i++)
#pragma unroll
                for (int j = 0; j < 4; j++)
                    acc[i][j] = fmaf(ar[i], br[j], acc[i][j]);
        }
        __syncthreads();
    }
#pragma unroll
    for (int i = 0; i < 4; i++) {
        int m = m0 + (ty << 2) + i;
#pragma unroll
        for (int j = 0; j < 4; j++) {
            int n = n0 + (tx << 2) + j;
            g_z0[(size_t)m * HH + n] = acc[i][j] + bxv[n] + bhv[n];
        }
    }
}

// ---------------------------------------------------------------------------
// Persistent sequential kernel. 96 CTAs, all co-resident (1/SM, big SMEM).
//   blocks [0,32):  layer 0 — h0_t = tanh(z0[t] + h0_{t-1} @ Wh0), 16-col slice
//   blocks [32,96): layer 1 — h1_t = tanh(b1 + h0_t@Wx1 + h1_{t-1}@Wh1), 8-col slice
// Cross-CTA sync: per-step flag counters (release fence + atomicAdd / acquire poll).
// ---------------------------------------------------------------------------
__global__ __launch_bounds__(256) void rnn_seq(
    const float* __restrict__ h_init,   // (L,B,H)
    const float* __restrict__ Wh0,
    const float* __restrict__ Wx1,
    const float* __restrict__ bx1,
    const float* __restrict__ Wh1,
    const float* __restrict__ bh1,
    float* __restrict__ out)            // [SEQ*B*H outputs][L*B*H h_n]
{
    extern __shared__ float sm[];
    float* hs  = sm;                    // [64][HSS]
    float* ws  = sm + 64 * HSS;         // weights slice
    float* aux = ws + 512 * 16;         // layer1: bias[8] + red[512]
    const int tid = threadIdx.x;

    if (blockIdx.x < NCTA0) {
        // ---------------- layer 0 ----------------
        const int n0 = blockIdx.x * NSL0;
        for (int i = tid; i < 512 * NSL0 / 4; i += 256) {
            int k = i >> 2, j = (i & 3) << 2;
            *(float4*)&ws[k * NSL0 + j] = *(const float4*)(Wh0 + (size_t)k * HH + n0 + j);
        }
        const int tn = (tid & 7) << 1;        // 0..14
        const int tb = (tid >> 3) << 1;       // 0..62

        for (int t = 0; t < SEQ; t++) {
            if (t > 0 && tid == 0) {
                while (ld_acq(&g_flag0[t - 1]) < NCTA0) __nanosleep(64);
            }
            __syncthreads();
            const float* hp = (t == 0) ? h_init : (g_h0 + (size_t)(t - 1) * BB * HH);
            for (int i = tid; i < BB * HH / 4; i += 256) {
                int b = i >> 7, kq = (i & 127) << 2;
                *(float4*)&hs[b * HSS + kq] = *(const float4*)(hp + (size_t)b * HH + kq);
            }
            __syncthreads();

            float a00 = 0.f, a01 = 0.f, a10 = 0.f, a11 = 0.f;
            const float* h0r = hs + tb * HSS;
            const float* h1r = hs + (tb + 1) * HSS;
#pragma unroll 4
            for (int k = 0; k < HH; k += 4) {
                float4 hv0 = *(const float4*)&h0r[k];
                float4 hv1 = *(const float4*)&h1r[k];
                float2 w0 = *(const float2*)&ws[(k + 0) * NSL0 + tn];
                float2 w1 = *(const float2*)&ws[(k + 1) * NSL0 + tn];
                float2 w2 = *(const float2*)&ws[(k + 2) * NSL0 + tn];
                float2 w3 = *(const float2*)&ws[(k + 3) * NSL0 + tn];
                a00 = fmaf(hv0.x, w0.x, a00); a01 = fmaf(hv0.x, w0.y, a01);
                a10 = fmaf(hv1.x, w0.x, a10); a11 = fmaf(hv1.x, w0.y, a11);
                a00 = fmaf(hv0.y, w1.x, a00); a01 = fmaf(hv0.y, w1.y, a01);
                a10 = fmaf(hv1.y, w1.x, a10); a11 = fmaf(hv1.y, w1.y, a11);
                a00 = fmaf(hv0.z, w2.x, a00); a01 = fmaf(hv0.z, w2.y, a01);
                a10 = fmaf(hv1.z, w2.x, a10); a11 = fmaf(hv1.z, w2.y, a11);
                a00 = fmaf(hv0.w, w3.x, a00); a01 = fmaf(hv0.w, w3.y, a01);
                a10 = fmaf(hv1.w, w3.x, a10); a11 = fmaf(hv1.w, w3.y, a11);
            }

            const float* z = g_z0 + (size_t)t * BB * HH;
            float* ho = g_h0 + (size_t)t * BB * HH;
            float v00 = tanhf(a00 + z[tb * HH + n0 + tn]);
            float v01 = tanhf(a01 + z[tb * HH + n0 + tn + 1]);
            float v10 = tanhf(a10 + z[(tb + 1) * HH + n0 + tn]);
            float v11 = tanhf(a11 + z[(tb + 1) * HH + n0 + tn + 1]);
            ho[tb * HH + n0 + tn]           = v00;
            ho[tb * HH + n0 + tn + 1]       = v01;
            ho[(tb + 1) * HH + n0 + tn]     = v10;
            ho[(tb + 1) * HH + n0 + tn + 1] = v11;
            if (t == SEQ - 1) {
                float* hn = out + (size_t)SEQ * BB * HH;   // h_n layer 0
                hn[tb * HH + n0 + tn]           = v00;
                hn[tb * HH + n0 + tn + 1]       = v01;
                hn[(tb + 1) * HH + n0 + tn]     = v10;
                hn[(tb + 1) * HH + n0 + tn + 1] = v11;
            }
            __syncthreads();
            if (tid == 0) { __threadfence(); atomicAdd(&g_flag0[t], 1); }
        }
    } else {
        // ---------------- layer 1 ----------------
        const int n0 = (blockIdx.x - NCTA0) * NSL1;
        float* wsx  = ws;               // [512][8]
        float* wsh  = ws + 512 * NSL1;  // [512][8]
        float* bias = aux;              // [8]
        float* red  = aux + 8;          // [128][4]
        for (int i = tid; i < 512 * NSL1 / 4; i += 256) {
            int k = i >> 1, j = (i & 1) << 2;
            *(float4*)&wsx[k * NSL1 + j] = *(const float4*)(Wx1 + (size_t)k * HH + n0 + j);
            *(float4*)&wsh[k * NSL1 + j] = *(const float4*)(Wh1 + (size_t)k * HH + n0 + j);
        }
        if (tid < NSL1) bias[tid] = bx1[n0 + tid] + bh1[n0 + tid];

        const int tn    = (tid & 3) << 1;        // 0..6
        const int tbi   = (tid >> 2) & 31;       // b0 = tbi, b1 = tbi+32
        const int kh    = tid >> 7;              // k-split half
        const int kbase = kh << 8;               // 0 or 256

        for (int t = 0; t < SEQ; t++) {
            if (tid == 0) {
                while (ld_acq(&g_flag0[t]) < NCTA0) __nanosleep(64);
                if (t > 0) while (ld_acq(&g_flag1[t - 1]) < NCTA1) __nanosleep(64);
            }
            __syncthreads();

            float a00 = 0.f, a01 = 0.f, a10 = 0.f, a11 = 0.f;

            // pass 1: h0_t @ Wx1
            {
                const float* hp = g_h0 + (size_t)t * BB * HH;
                for (int i = tid; i < BB * HH / 4; i += 256) {
                    int b = i >> 7, kq = (i & 127) << 2;
                    *(float4*)&hs[b * HSS + kq] = *(const float4*)(hp + (size_t)b * HH + kq);
                }
                __syncthreads();
                const float* h0r = hs + tbi * HSS + kbase;
                const float* h1r = hs + (tbi + 32) * HSS + kbase;
#pragma unroll 4
                for (int k = 0; k < 256; k += 4) {
                    float4 hv0 = *(const float4*)&h0r[k];
                    float4 hv1 = *(const float4*)&h1r[k];
                    float2 w0 = *(const float2*)&wsx[(kbase + k + 0) * NSL1 + tn];
                    float2 w1 = *(const float2*)&wsx[(kbase + k + 1) * NSL1 + tn];
                    float2 w2 = *(const float2*)&wsx[(kbase + k + 2) * NSL1 + tn];
                    float2 w3 = *(const float2*)&wsx[(kbase + k + 3) * NSL1 + tn];
                    a00 = fmaf(hv0.x, w0.x, a00); a01 = fmaf(hv0.x, w0.y, a01);
                    a10 = fmaf(hv1.x, w0.x, a10); a11 = fmaf(hv1.x, w0.y, a11);
                    a00 = fmaf(hv0.y, w1.x, a00); a01 = fmaf(hv0.y, w1.y, a01);
                    a10 = fmaf(hv1.y, w1.x, a10); a11 = fmaf(hv1.y, w1.y, a11);
                    a00 = fmaf(hv0.z, w2.x, a00); a01 = fmaf(hv0.z, w2.y, a01);
                    a10 = fmaf(hv1.z, w2.x, a10); a11 = fmaf(hv1.z, w2.y, a11);
                    a00 = fmaf(hv0.w, w3.x, a00); a01 = fmaf(hv0.w, w3.y, a01);
                    a10 = fmaf(hv1.w, w3.x, a10); a11 = fmaf(hv1.w, w3.y, a11);
                }
            }
            __syncthreads();

            // pass 2: h1_{t-1} @ Wh1 (h1 history lives in `out`)
            {
                const float* hq = (t == 0) ? (h_init + BB * HH)
                                           : (out + (size_t)(t - 1) * BB * HH);
                for (int i = tid; i < BB * HH / 4; i += 256) {
                    int b = i >> 7, kq = (i & 127) << 2;
                    *(float4*)&hs[b * HSS + kq] = *(const float4*)(hq + (size_t)b * HH + kq);
                }
                __syncthreads();
                const float* h0r = hs + tbi * HSS + kbase;
                const float* h1r = hs + (tbi + 32) * HSS + kbase;
#pragma unroll 4
                for (int k = 0; k < 256; k += 4) {
                    float4 hv0 = *(const float4*)&h0r[k];
                    float4 hv1 = *(const float4*)&h1r[k];
                    float2 w0 = *(const float2*)&wsh[(kbase + k + 0) * NSL1 + tn];
                    float2 w1 = *(const float2*)&wsh[(kbase + k + 1) * NSL1 + tn];
                    float2 w2 = *(const float2*)&wsh[(kbase + k + 2) * NSL1 + tn];
                    float2 w3 = *(const float2*)&wsh[(kbase + k + 3) * NSL1 + tn];
                    a00 = fmaf(hv0.x, w0.x, a00); a01 = fmaf(hv0.x, w0.y, a01);
                    a10 = fmaf(hv1.x, w0.x, a10); a11 = fmaf(hv1.x, w0.y, a11);
                    a00 = fmaf(hv0.y, w1.x, a00); a01 = fmaf(hv0.y, w1.y, a01);
                    a10 = fmaf(hv1.y, w1.x, a10); a11 = fmaf(hv1.y, w1.y, a11);
                    a00 = fmaf(hv0.z, w2.x, a00); a01 = fmaf(hv0.z, w2.y, a01);
                    a10 = fmaf(hv1.z, w2.x, a10); a11 = fmaf(hv1.z, w2.y, a11);
                    a00 = fmaf(hv0.w, w3.x, a00); a01 = fmaf(hv0.w, w3.y, a01);
                    a10 = fmaf(hv1.w, w3.x, a10); a11 = fmaf(hv1.w, w3.y, a11);
                }
            }

            // reduce the two K halves, epilogue
            if (kh == 1) {
                float* r = red + (tid - 128) * 4;
                r[0] = a00; r[1] = a01; r[2] = a10; r[3] = a11;
            }
            __syncthreads();
            if (kh == 0) {
                const float* r = red + tid * 4;
                float v00 = tanhf(a00 + r[0] + bias[tn]);
                float v01 = tanhf(a01 + r[1] + bias[tn + 1]);
                float v10 = tanhf(a10 + r[2] + bias[tn]);
                float v11 = tanhf(a11 + r[3] + bias[tn + 1]);
                float* o = out + (size_t)t * BB * HH;
                o[tbi * HH + n0 + tn]            = v00;
                o[tbi * HH + n0 + tn + 1]        = v01;
                o[(tbi + 32) * HH + n0 + tn]     = v10;
                o[(tbi + 32) * HH + n0 + tn + 1] = v11;
                if (t == SEQ - 1) {
                    float* hn = out + (size_t)SEQ * BB * HH + BB * HH;  // h_n layer 1
                    hn[tbi * HH + n0 + tn]            = v00;
                    hn[tbi * HH + n0 + tn + 1]        = v01;
                    hn[(tbi + 32) * HH + n0 + tn]     = v10;
                    hn[(tbi + 32) * HH + n0 + tn + 1] = v11;
                }
            }
            __syncthreads();
            if (tid == 0) { __threadfence(); atomicAdd(&g_flag1[t], 1); }
        }
    }
}

#define SMEM_BYTES ((64 * HSS + 512 * 16 + 8 + 512) * (int)sizeof(float))

extern "C" void kernel_launch(void* const* d_in, const int* in_sizes, int n_in,
                              void* d_out, int out_size)
{
    const float* x   = (const float*)d_in[0];
    const float* h0  = (const float*)d_in[1];
    const float* Wx0 = (const float*)d_in[2];
    const float* bx0 = (const float*)d_in[3];
    const float* Wh0 = (const float*)d_in[4];
    const float* bh0 = (const float*)d_in[5];
    const float* Wx1 = (const float*)d_in[6];
    const float* bx1 = (const float*)d_in[7];
    const float* Wh1 = (const float*)d_in[8];
    const float* bh1 = (const float*)d_in[9];
    float* out = (float*)d_out;

    (void)in_sizes; (void)n_in; (void)out_size; (void)x;

    init_flags<<<4, 256>>>();

    dim3 gz((SEQ * BB) / 64, HH / 64);
    precompute_z0<<<gz, 256>>>(x, Wx0, bx0, bh0);

    cudaFuncSetAttribute(rnn_seq, cudaFuncAttributeMaxDynamicSharedMemorySize,
                         SMEM_BYTES);
    rnn_seq<<<NCTA0 + NCTA1, 256, SMEM_BYTES>>>(h0, Wh0, Wx1, bx1, Wh1, bh1, out);
}

// round 3
// speedup vs baseline: 2.9388x; 2.9388x over previous
#include <cuda_runtime.h>
#include <math.h>
#include <stdint.h>

#define SEQ 1024
#define BB  64
#define DD  512
#define HH  512

#define NCTA0 32
#define NSL0  16   // cols per layer-0 CTA
#define NCTA1 64
#define NSL1  8    // cols per layer-1 CTA

#define HSS 516    // padded shared row stride (floats) for h

typedef unsigned long long u64;

// Scratch (allocation-free rule: __device__ globals)
__device__ float g_z0[SEQ * BB * HH];   // x@Wx0 + bx0 + bh0
__device__ float g_h0[SEQ * BB * HH];   // layer-0 hidden history
__device__ int   g_flag0[SEQ];
__device__ int   g_flag1[SEQ];

// ---------------------------------------------------------------- helpers
__device__ __forceinline__ int ld_acq(const int* p) {
    int v;
    asm volatile("ld.acquire.gpu.s32 %0, [%1];" : "=r"(v) : "l"(p) : "memory");
    return v;
}
__device__ __forceinline__ u64 dup2(float x) {
    u64 r;
    asm("mov.b64 %0, {%1, %1};" : "=l"(r) : "f"(x));
    return r;
}
__device__ __forceinline__ void fma2(u64& acc, u64 a, u64 b) {
    asm("fma.rn.f32x2 %0, %1, %2, %0;" : "+l"(acc) : "l"(a), "l"(b));
}
__device__ __forceinline__ u64 add2(u64 a, u64 b) {
    u64 r;
    asm("add.rn.f32x2 %0, %1, %2;" : "=l"(r) : "l"(a), "l"(b));
    return r;
}
__device__ __forceinline__ float2 unp2(u64 v) {
    float2 f;
    asm("mov.b64 {%0, %1}, %2;" : "=f"(f.x), "=f"(f.y) : "l"(v));
    return f;
}
__device__ __forceinline__ void cp16(uint32_t s, const void* g) {
    asm volatile("cp.async.cg.shared.global [%0], [%1], 16;" :: "r"(s), "l"(g));
}
__device__ __forceinline__ void cp_wait_all() {
    asm volatile("cp.async.commit_group;\n\tcp.async.wait_group 0;" ::: "memory");
}

// Stage h (64 x 512 f32) from global into padded SMEM rows via cp.async (L1-bypass .cg)
__device__ __forceinline__ void stage_h(float* hs, const float* src, int tid) {
    uint32_t s0 = (uint32_t)__cvta_generic_to_shared(hs);
#pragma unroll 4
    for (int i = tid; i < BB * HH / 4; i += 256) {
        int b = i >> 7, kq = (i & 127) << 2;
        cp16(s0 + (uint32_t)(b * HSS + kq) * 4u, src + b * HH + kq);
    }
    cp_wait_all();
}

// Packed-fp32 GEMV accumulation: 2 batch rows x 4 cols micro-tile.
// acc[0]=b0/cols(0,1) acc[1]=b0/cols(2,3) acc[2]=b1/(0,1) acc[3]=b1/(2,3)
// wcol points at &ws[col_quad*4]; row stride NS floats.
template<int NS>
__device__ __forceinline__ void gemv_acc(u64 acc[4], const float* hr0, const float* hr1,
                                         const float* wcol, int kbeg, int kend)
{
#pragma unroll 4
    for (int k = kbeg; k < kend; k += 4) {
        float4 h0 = *(const float4*)(hr0 + k);
        float4 h1 = *(const float4*)(hr1 + k);
        ulonglong2 w0 = *(const ulonglong2*)(wcol + (size_t)(k + 0) * NS);
        ulonglong2 w1 = *(const ulonglong2*)(wcol + (size_t)(k + 1) * NS);
        ulonglong2 w2 = *(const ulonglong2*)(wcol + (size_t)(k + 2) * NS);
        ulonglong2 w3 = *(const ulonglong2*)(wcol + (size_t)(k + 3) * NS);
        u64 d;
        d = dup2(h0.x); fma2(acc[0], d, w0.x); fma2(acc[1], d, w0.y);
        d = dup2(h1.x); fma2(acc[2], d, w0.x); fma2(acc[3], d, w0.y);
        d = dup2(h0.y); fma2(acc[0], d, w1.x); fma2(acc[1], d, w1.y);
        d = dup2(h1.y); fma2(acc[2], d, w1.x); fma2(acc[3], d, w1.y);
        d = dup2(h0.z); fma2(acc[0], d, w2.x); fma2(acc[1], d, w2.y);
        d = dup2(h1.z); fma2(acc[2], d, w2.x); fma2(acc[3], d, w2.y);
        d = dup2(h0.w); fma2(acc[0], d, w3.x); fma2(acc[1], d, w3.y);
        d = dup2(h1.w); fma2(acc[2], d, w3.x); fma2(acc[3], d, w3.y);
    }
}

__global__ void init_flags() {
    int i = blockIdx.x * blockDim.x + threadIdx.x;
    if (i < SEQ) { g_flag0[i] = 0; g_flag1[i] = 0; }
}

// ---------------------------------------------------------------------------
// Precompute Z0 = X @ Wx0 + bx0 + bh0 (packed fp32 inner).
// ---------------------------------------------------------------------------
__global__ __launch_bounds__(256) void precompute_z0(
    const float* __restrict__ X,
    const float* __restrict__ W,
    const float* __restrict__ bxv,
    const float* __restrict__ bhv)
{
    __shared__ float As[16][64];
    __shared__ float Bs[16][64];
    const int tid = threadIdx.x;
    const int tx = tid & 15;
    const int ty = tid >> 4;
    const int m0 = blockIdx.x * 64;
    const int n0 = blockIdx.y * 64;
    const int lm = tid >> 2;
    const int lk = (tid & 3) << 2;
    const int lr = tid >> 4;
    const int lc = (tid & 15) << 2;

    u64 acc[4][2];
#pragma unroll
    for (int i = 0; i < 4; i++) { acc[i][0] = 0ULL; acc[i][1] = 0ULL; }

    for (int kc = 0; kc < DD; kc += 16) {
        float4 a4 = *(const float4*)(X + (size_t)(m0 + lm) * DD + kc + lk);
        float4 b4 = *(const float4*)(W + (size_t)(kc + lr) * HH + n0 + lc);
        As[lk + 0][lm] = a4.x;
        As[lk + 1][lm] = a4.y;
        As[lk + 2][lm] = a4.z;
        As[lk + 3][lm] = a4.w;
        *(float4*)&Bs[lr][lc] = b4;
        __syncthreads();
#pragma unroll
        for (int kk = 0; kk < 16; kk++) {
            float4 av = *(const float4*)&As[kk][ty << 2];
            ulonglong2 bq = *(const ulonglong2*)&Bs[kk][tx << 2];
            u64 d;
            d = dup2(av.x); fma2(acc[0][0], d, bq.x); fma2(acc[0][1], d, bq.y);
            d = dup2(av.y); fma2(acc[1][0], d, bq.x); fma2(acc[1][1], d, bq.y);
            d = dup2(av.z); fma2(acc[2][0], d, bq.x); fma2(acc[2][1], d, bq.y);
            d = dup2(av.w); fma2(acc[3][0], d, bq.x); fma2(acc[3][1], d, bq.y);
        }
        __syncthreads();
    }
    const int n = n0 + (tx << 2);
    float4 bx4 = *(const float4*)(bxv + n);
    float4 bh4 = *(const float4*)(bhv + n);
#pragma unroll
    for (int i = 0; i < 4; i++) {
        int m = m0 + (ty << 2) + i;
        float2 c0 = unp2(acc[i][0]);
        float2 c1 = unp2(acc[i][1]);
        float4 o;
        o.x = c0.x + bx4.x + bh4.x;
        o.y = c0.y + bx4.y + bh4.y;
        o.z = c1.x + bx4.z + bh4.z;
        o.w = c1.y + bx4.w + bh4.w;
        *(float4*)(g_z0 + (size_t)m * HH + n) = o;
    }
}

// ---------------------------------------------------------------------------
// Persistent sequential kernel. 96 CTAs (1/SM).
//   blocks [0,32):  layer 0, 16-col slice, K split in 2 across thread halves
//   blocks [32,96): layer 1, 8-col slice, K split in 4; pass order: Wh1 then Wx1
// ---------------------------------------------------------------------------
__global__ __launch_bounds__(256) void rnn_seq(
    const float* __restrict__ h_init,
    const float* __restrict__ Wh0,
    const float* __restrict__ Wx1,
    const float* __restrict__ bx1,
    const float* __restrict__ Wh1,
    const float* __restrict__ bh1,
    float* __restrict__ out)
{
    extern __shared__ float sm[];
    float* hs   = sm;                         // [64][HSS]
    float* ws   = sm + 64 * HSS;              // 8192 floats of weights
    u64*   red  = (u64*)(ws + 8192);          // up to 768 u64
    float* bias = (float*)(red + 768);        // 8 floats (layer 1)
    const int tid = threadIdx.x;

    if (blockIdx.x < NCTA0) {
        // ------------------------- layer 0 -------------------------
        const int n0 = blockIdx.x * NSL0;
        for (int i = tid; i < 512 * NSL0 / 4; i += 256) {
            int k = i >> 2, j = (i & 3) << 2;
            *(float4*)&ws[k * NSL0 + j] = *(const float4*)(Wh0 + (size_t)k * HH + n0 + j);
        }
        const int nq = tid & 3;               // col quad 0..3
        const int bp = (tid >> 2) & 31;       // batch pair 0..31
        const int kh = tid >> 7;              // k half
        const int b0 = bp << 1;
        const int slot = tid & 127;
        const float* wcol = ws + (nq << 2);

        for (int t = 0; t < SEQ; t++) {
            if (t > 0 && tid == 0) {
                while (ld_acq(&g_flag0[t - 1]) < NCTA0) __nanosleep(32);
            }
            __syncthreads();
            const float* hp = (t == 0) ? h_init : (g_h0 + (size_t)(t - 1) * BB * HH);
            stage_h(hs, hp, tid);
            __syncthreads();

            u64 acc[4] = {0ULL, 0ULL, 0ULL, 0ULL};
            gemv_acc<NSL0>(acc, hs + b0 * HSS, hs + (b0 + 1) * HSS,
                           wcol, kh << 8, (kh << 8) + 256);

            if (kh) {
                u64* r = red + slot * 4;
                r[0] = acc[0]; r[1] = acc[1]; r[2] = acc[2]; r[3] = acc[3];
            }
            __syncthreads();
            if (!kh) {
                const u64* r = red + slot * 4;
#pragma unroll
                for (int j = 0; j < 4; j++) acc[j] = add2(acc[j], r[j]);

                const float* z = g_z0 + (size_t)t * BB * HH;
                float4 z0v = *(const float4*)(z + b0 * HH + n0 + (nq << 2));
                float4 z1v = *(const float4*)(z + (b0 + 1) * HH + n0 + (nq << 2));
                float2 p00 = unp2(acc[0]), p01 = unp2(acc[1]);
                float2 p10 = unp2(acc[2]), p11 = unp2(acc[3]);
                float4 v0, v1;
                v0.x = tanhf(p00.x + z0v.x); v0.y = tanhf(p00.y + z0v.y);
                v0.z = tanhf(p01.x + z0v.z); v0.w = tanhf(p01.y + z0v.w);
                v1.x = tanhf(p10.x + z1v.x); v1.y = tanhf(p10.y + z1v.y);
                v1.z = tanhf(p11.x + z1v.z); v1.w = tanhf(p11.y + z1v.w);
                float* ho = g_h0 + (size_t)t * BB * HH;
                *(float4*)(ho + b0 * HH + n0 + (nq << 2))       = v0;
                *(float4*)(ho + (b0 + 1) * HH + n0 + (nq << 2)) = v1;
                if (t == SEQ - 1) {
                    float* hn = out + (size_t)SEQ * BB * HH;
                    *(float4*)(hn + b0 * HH + n0 + (nq << 2))       = v0;
                    *(float4*)(hn + (b0 + 1) * HH + n0 + (nq << 2)) = v1;
                }
            }
            __syncthreads();
            if (tid == 0) { __threadfence(); atomicAdd(&g_flag0[t], 1); }
        }
    } else {
        // ------------------------- layer 1 -------------------------
        const int n0 = (blockIdx.x - NCTA0) * NSL1;
        float* wsx = ws;                      // [512][8]
        float* wsh = ws + 512 * NSL1;         // [512][8]
        for (int i = tid; i < 512 * NSL1 / 4; i += 256) {
            int k = i >> 1, j = (i & 1) << 2;
            *(float4*)&wsx[k * NSL1 + j] = *(const float4*)(Wx1 + (size_t)k * HH + n0 + j);
            *(float4*)&wsh[k * NSL1 + j] = *(const float4*)(Wh1 + (size_t)k * HH + n0 + j);
        }
        if (tid < NSL1) bias[tid] = bx1[n0 + tid] + bh1[n0 + tid];

        const int nq = tid & 1;               // col quad 0..1
        const int bp = (tid >> 1) & 31;       // batch pair
        const int kh = tid >> 6;              // k quarter 0..3
        const int b0 = bp << 1;
        const int slot = tid & 63;
        const float* wcx = wsx + (nq << 2);
        const float* wch = wsh + (nq << 2);

        for (int t = 0; t < SEQ; t++) {
            if (t > 0 && tid == 0) {
                while (ld_acq(&g_flag1[t - 1]) < NCTA1) __nanosleep(32);
            }
            __syncthreads();

            // pass A: h1_{t-1} @ Wh1  (available first — hides layer-0 latency)
            const float* hq = (t == 0) ? (h_init + BB * HH)
                                       : (out + (size_t)(t - 1) * BB * HH);
            stage_h(hs, hq, tid);
            __syncthreads();

            u64 acc[4] = {0ULL, 0ULL, 0ULL, 0ULL};
            gemv_acc<NSL1>(acc, hs + b0 * HSS, hs + (b0 + 1) * HSS,
                           wch, kh << 7, (kh << 7) + 128);
            __syncthreads();   // everyone done reading hs (h1)

            // pass B: h0_t @ Wx1
            if (tid == 0) {
                while (ld_acq(&g_flag0[t]) < NCTA0) __nanosleep(32);
            }
            __syncthreads();
            stage_h(hs, g_h0 + (size_t)t * BB * HH, tid);
            __syncthreads();
            gemv_acc<NSL1>(acc, hs + b0 * HSS, hs + (b0 + 1) * HSS,
                           wcx, kh << 7, (kh << 7) + 128);

            if (kh) {
                u64* r = red + ((size_t)(kh - 1) * 64 + slot) * 4;
                r[0] = acc[0]; r[1] = acc[1]; r[2] = acc[2]; r[3] = acc[3];
            }
            __syncthreads();
            if (!kh) {
#pragma unroll
                for (int q = 0; q < 3; q++) {
                    const u64* r = red + ((size_t)q * 64 + slot) * 4;
#pragma unroll
                    for (int j = 0; j < 4; j++) acc[j] = add2(acc[j], r[j]);
                }
                float bb0 = bias[(nq << 2) + 0], bb1 = bias[(nq << 2) + 1];
                float bb2 = bias[(nq << 2) + 2], bb3 = bias[(nq << 2) + 3];
                float2 p00 = unp2(acc[0]), p01 = unp2(acc[1]);
                float2 p10 = unp2(acc[2]), p11 = unp2(acc[3]);
                float4 v0, v1;
                v0.x = tanhf(p00.x + bb0); v0.y = tanhf(p00.y + bb1);
                v0.z = tanhf(p01.x + bb2); v0.w = tanhf(p01.y + bb3);
                v1.x = tanhf(p10.x + bb0); v1.y = tanhf(p10.y + bb1);
                v1.z = tanhf(p11.x + bb2); v1.w = tanhf(p11.y + bb3);
                float* o = out + (size_t)t * BB * HH;
                *(float4*)(o + b0 * HH + n0 + (nq << 2))       = v0;
                *(float4*)(o + (b0 + 1) * HH + n0 + (nq << 2)) = v1;
                if (t == SEQ - 1) {
                    float* hn = out + (size_t)SEQ * BB * HH + BB * HH;
                    *(float4*)(hn + b0 * HH + n0 + (nq << 2))       = v0;
                    *(float4*)(hn + (b0 + 1) * HH + n0 + (nq << 2)) = v1;
                }
            }
            __syncthreads();
            if (tid == 0) { __threadfence(); atomicAdd(&g_flag1[t], 1); }
        }
    }
}

#define SMEM_BYTES ((64 * HSS + 8192) * (int)sizeof(float) + 768 * 8 + 64)

extern "C" void kernel_launch(void* const* d_in, const int* in_sizes, int n_in,
                              void* d_out, int out_size)
{
    const float* x   = (const float*)d_in[0];
    const float* h0  = (const float*)d_in[1];
    const float* Wx0 = (const float*)d_in[2];
    const float* bx0 = (const float*)d_in[3];
    const float* Wh0 = (const float*)d_in[4];
    const float* bh0 = (const float*)d_in[5];
    const float* Wx1 = (const float*)d_in[6];
    const float* bx1 = (const float*)d_in[7];
    const float* Wh1 = (const float*)d_in[8];
    const float* bh1 = (const float*)d_in[9];
    float* out = (float*)d_out;
    (void)in_sizes; (void)n_in; (void)out_size;

    init_flags<<<4, 256>>>();

    dim3 gz((SEQ * BB) / 64, HH / 64);
    precompute_z0<<<gz, 256>>>(x, Wx0, bx0, bh0);

    static int attr_set = 0;
    if (!attr_set) {
        cudaFuncSetAttribute(rnn_seq, cudaFuncAttributeMaxDynamicSharedMemorySize,
                             SMEM_BYTES);
        attr_set = 1;
    }
    rnn_seq<<<NCTA0 + NCTA1, 256, SMEM_BYTES>>>(h0, Wh0, Wx1, bx1, Wh1, bh1, out);
}